// round 4
// baseline (speedup 1.0000x reference)
#include <cuda_runtime.h>
#include <math.h>
#include <stdint.h>

// Problem constants (fixed by setup_inputs: x[2048,512], memories[8192,512], k=5, beta=1, steps=2)
#define BQ 2048
#define NM 8192
#define DD 512
#define NCOL 5
#define BISECT_ITERS 100
#define CAND_CAP 2040

// ---------------- scratch (device globals; no runtime allocation) ----------------
__device__ float g_X[(size_t)BQ * NM];                 // logits -dists  (67 MB)
__device__ float g_P[(size_t)NCOL * BQ * NM];          // ksm coefficient planes (335 MB)
__device__ float g_L[(size_t)BQ * NM];                 // hopfield logits/weights (67 MB)
__device__ float g_Z[(size_t)NCOL * BQ * DD];          // result planes (21 MB)
__device__ float g_m2[NM];
__device__ float g_x2[BQ];
__device__ float g_zn2[BQ];
__device__ float g_par[BQ * 8];                        // per row: max, sumexp, nu2..nu5

// ---------------- small helpers ----------------
__device__ __forceinline__ float sigmoidf_(float t) {
    return 1.0f / (1.0f + __expf(-t));
}

// ---------------- row squared-norms (fp32; order irrelevant: shift-invariant downstream) ----------------
__global__ void rownorm2_kernel(const float* __restrict__ A, float* __restrict__ out, int cols)
{
    int r = blockIdx.x;
    const float* a = A + (size_t)r * cols;
    float s = 0.f;
    for (int c = threadIdx.x; c < cols; c += blockDim.x) { float v = a[c]; s = fmaf(v, v, s); }
#pragma unroll
    for (int o = 16; o; o >>= 1) s += __shfl_xor_sync(0xffffffffu, s, o);
    __shared__ float red[4];
    if ((threadIdx.x & 31) == 0) red[threadIdx.x >> 5] = s;
    __syncthreads();
    if (threadIdx.x == 0) out[r] = red[0] + red[1] + red[2] + red[3];
}

// ---------------- NT SGEMM (fp32) with fused distance epilogue ----------------
// Mirrors reference association exactly: d = (arow[i] + bcol[j]) - 2*t;  logit = -max(d, 0)
__global__ void __launch_bounds__(256, 2)
sgemm_nt_ep(const float* __restrict__ A, const float* __restrict__ Bm,
            const float* __restrict__ arow, const float* __restrict__ bcol,
            float* __restrict__ C, int M, int N, int K)
{
    __shared__ float As[16][128];
    __shared__ float Bs[16][128];
    const int bm = blockIdx.y * 128;
    const int bn = blockIdx.x * 128;
    const int tid = threadIdx.x;
    const int tx = tid & 15;
    const int ty = tid >> 4;
    const int lr = tid >> 2;
    const int lc = (tid & 3) << 2;

    float acc[8][8];
#pragma unroll
    for (int i = 0; i < 8; i++)
#pragma unroll
        for (int j = 0; j < 8; j++) acc[i][j] = 0.f;

    for (int k0 = 0; k0 < K; k0 += 16) {
#pragma unroll
        for (int h = 0; h < 2; h++) {
            int r = lr + h * 64;
            float4 va = *(const float4*)(A + (size_t)(bm + r) * K + k0 + lc);
            As[lc + 0][r] = va.x; As[lc + 1][r] = va.y; As[lc + 2][r] = va.z; As[lc + 3][r] = va.w;
            float4 vb = *(const float4*)(Bm + (size_t)(bn + r) * K + k0 + lc);
            Bs[lc + 0][r] = vb.x; Bs[lc + 1][r] = vb.y; Bs[lc + 2][r] = vb.z; Bs[lc + 3][r] = vb.w;
        }
        __syncthreads();
#pragma unroll
        for (int kk = 0; kk < 16; kk++) {
            float a[8], b[8];
            float4 a0 = *(const float4*)&As[kk][ty * 8];
            float4 a1 = *(const float4*)&As[kk][ty * 8 + 4];
            float4 b0 = *(const float4*)&Bs[kk][tx * 8];
            float4 b1 = *(const float4*)&Bs[kk][tx * 8 + 4];
            a[0]=a0.x; a[1]=a0.y; a[2]=a0.z; a[3]=a0.w; a[4]=a1.x; a[5]=a1.y; a[6]=a1.z; a[7]=a1.w;
            b[0]=b0.x; b[1]=b0.y; b[2]=b0.z; b[3]=b0.w; b[4]=b1.x; b[5]=b1.y; b[6]=b1.z; b[7]=b1.w;
#pragma unroll
            for (int i = 0; i < 8; i++)
#pragma unroll
                for (int j = 0; j < 8; j++) acc[i][j] = fmaf(a[i], b[j], acc[i][j]);
        }
        __syncthreads();
    }

#pragma unroll
    for (int i = 0; i < 8; i++) {
        int gr = bm + ty * 8 + i;
        float ar = arow[gr];
#pragma unroll
        for (int j = 0; j < 8; j += 4) {
            int gc = bn + tx * 8 + j;
            float4 o;
            // reference op order: d = (x2 + m2) - 2*dot; max(d,0); logit = -d
            o.x = -fmaxf((ar + bcol[gc + 0]) - 2.f * acc[i][j + 0], 0.f);
            o.y = -fmaxf((ar + bcol[gc + 1]) - 2.f * acc[i][j + 1], 0.f);
            o.z = -fmaxf((ar + bcol[gc + 2]) - 2.f * acc[i][j + 2], 0.f);
            o.w = -fmaxf((ar + bcol[gc + 3]) - 2.f * acc[i][j + 3], 0.f);
            *(float4*)(C + (size_t)gr * N + gc) = o;
        }
    }
}

// ---------------- NN SGEMM (fp32): C[M,N] = A[M,K] @ B[K,N] ----------------
__global__ void __launch_bounds__(128)
sgemm_nn(const float* __restrict__ A, const float* __restrict__ Bm,
         float* __restrict__ C, int M, int N, int K)
{
    __shared__ float As[16][64];
    __shared__ float Bs[16][64];
    const int bm = blockIdx.y * 64;
    const int bn = blockIdx.x * 64;
    const int tid = threadIdx.x;
    const int tx = tid & 15;      // col group *4
    const int ty = tid >> 4;      // row group *8
    const int ar_ = tid >> 2;     // 0..31
    const int ac = (tid & 3) << 2;
    const int bkr = tid >> 4;     // 0..7
    const int bc = (tid & 15) << 2;

    float acc[8][4];
#pragma unroll
    for (int i = 0; i < 8; i++)
#pragma unroll
        for (int j = 0; j < 4; j++) acc[i][j] = 0.f;

    for (int k0 = 0; k0 < K; k0 += 16) {
#pragma unroll
        for (int h = 0; h < 2; h++) {
            int r = ar_ + h * 32;
            float4 va = *(const float4*)(A + (size_t)(bm + r) * K + k0 + ac);
            As[ac + 0][r] = va.x; As[ac + 1][r] = va.y; As[ac + 2][r] = va.z; As[ac + 3][r] = va.w;
            int kr = bkr + h * 8;
            float4 vb = *(const float4*)(Bm + (size_t)(k0 + kr) * N + bn + bc);
            *(float4*)&Bs[kr][bc] = vb;
        }
        __syncthreads();
#pragma unroll
        for (int kk = 0; kk < 16; kk++) {
            float4 a0 = *(const float4*)&As[kk][ty * 8];
            float4 a1 = *(const float4*)&As[kk][ty * 8 + 4];
            float4 b0 = *(const float4*)&Bs[kk][tx * 4];
            float a[8] = {a0.x, a0.y, a0.z, a0.w, a1.x, a1.y, a1.z, a1.w};
            float b[4] = {b0.x, b0.y, b0.z, b0.w};
#pragma unroll
            for (int i = 0; i < 8; i++)
#pragma unroll
                for (int j = 0; j < 4; j++) acc[i][j] = fmaf(a[i], b[j], acc[i][j]);
        }
        __syncthreads();
    }

#pragma unroll
    for (int i = 0; i < 8; i++) {
        int gr = bm + ty * 8 + i;
        float4 o = make_float4(acc[i][0], acc[i][1], acc[i][2], acc[i][3]);
        *(float4*)(C + (size_t)gr * N + bn + tx * 4) = o;
    }
}

// ---------------- per-row stats: max, sumexp, top-6, LML bisection ----------------
__global__ void __launch_bounds__(256)
stats_kernel(const float* __restrict__ X, float* __restrict__ par)
{
    __shared__ float s_row[NM];
    __shared__ float s_cand[CAND_CAP + 8];
    __shared__ float s_redf[8];
    __shared__ int   s_redi[8];
    __shared__ float s_topv[8];
    __shared__ int   s_cnt;
    __shared__ float s_max, s_sum;
    __shared__ int   s_total;

    const int b = blockIdx.x;
    const int tid = threadIdx.x;
    const int lane = tid & 31;
    const int w = tid >> 5;
    const float* x = X + (size_t)b * NM;

    // load row + local max
    float lmax = -3.402823466e38f;
    for (int i = tid; i < NM; i += 256) { float v = x[i]; s_row[i] = v; lmax = fmaxf(lmax, v); }
#pragma unroll
    for (int o = 16; o; o >>= 1) lmax = fmaxf(lmax, __shfl_xor_sync(0xffffffffu, lmax, o));
    if (lane == 0) s_redf[w] = lmax;
    __syncthreads();
    if (tid == 0) {
        float m = s_redf[0];
        for (int i = 1; i < 8; i++) m = fmaxf(m, s_redf[i]);
        s_max = m;
    }
    __syncthreads();
    const float rmax = s_max;

    // sum exp(x - max)
    float ls = 0.f;
    for (int i = tid; i < NM; i += 256) ls += __expf(s_row[i] - rmax);
#pragma unroll
    for (int o = 16; o; o >>= 1) ls += __shfl_xor_sync(0xffffffffu, ls, o);
    __syncthreads();
    if (lane == 0) s_redf[w] = ls;
    __syncthreads();
    if (tid == 0) {
        float t = 0.f;
        for (int i = 0; i < 8; i++) t += s_redf[i];
        s_sum = t;
    }

    // top-6 extraction (argmax passes; extracted entries replaced with -inf)
    for (int t6 = 0; t6 < 6; t6++) {
        __syncthreads();
        float lv = -3.402823466e38f; int li = 0;
        for (int i = tid; i < NM; i += 256) { float v = s_row[i]; if (v > lv) { lv = v; li = i; } }
#pragma unroll
        for (int o = 16; o; o >>= 1) {
            float ov = __shfl_xor_sync(0xffffffffu, lv, o);
            int   oi = __shfl_xor_sync(0xffffffffu, li, o);
            if (ov > lv || (ov == lv && oi < li)) { lv = ov; li = oi; }
        }
        if (lane == 0) { s_redf[w] = lv; s_redi[w] = li; }
        __syncthreads();
        if (tid == 0) {
            float bv = s_redf[0]; int bi = s_redi[0];
            for (int i = 1; i < 8; i++)
                if (s_redf[i] > bv || (s_redf[i] == bv && s_redi[i] < bi)) { bv = s_redf[i]; bi = s_redi[i]; }
            s_topv[t6] = bv;
            s_row[bi] = -3.402823466e38f;
        }
    }
    __syncthreads();

    // candidate compaction: values > top6 - 34  (dropped-sigmoid mass <= 8192*e^-27 ~ 1.5e-8)
    const float thr = s_topv[5] - 34.0f;
    if (tid == 0) s_cnt = 0;
    __syncthreads();
    for (int i = tid; i < NM; i += 256) {
        float v = s_row[i];
        if (v > thr) {
            int p = atomicAdd(&s_cnt, 1);
            if (p < CAND_CAP) s_cand[p] = v;
        }
    }
    __syncthreads();
    if (tid == 0) {
        int base = min(s_cnt, CAND_CAP);
        for (int i = 0; i < 6; i++) s_cand[base + i] = s_topv[i];
        s_total = base + 6;
    }
    __syncthreads();
    const int total = s_total;

    // bisection for nu_k, k = 2..5 (one warp each). Mirrors reference decisions.
    if (w < 4) {
        const int kk = w + 2;
        float lo = -s_topv[kk - 1] - 7.0f;
        float hi = -s_topv[kk] + 7.0f;
        for (int it = 0; it < BISECT_ITERS; it++) {
            float mid = 0.5f * (lo + hi);
            float s = 0.f;
            for (int c = lane; c < total; c += 32) s += sigmoidf_(s_cand[c] + mid);
#pragma unroll
            for (int o = 16; o; o >>= 1) s += __shfl_xor_sync(0xffffffffu, s, o);
            float f = s - (float)kk;
            if (f < 0.f) lo = mid; else hi = mid;
        }
        if (lane == 0) par[b * 8 + 2 + (kk - 2)] = 0.5f * (lo + hi);
    }
    if (tid == 0) {
        par[b * 8 + 0] = rmax;
        par[b * 8 + 1] = s_sum;
    }
}

// ---------------- coefficient planes: p, y2-p, y3-y2, y4-y3, y5-y4 ----------------
__global__ void planes_kernel(const float* __restrict__ X, const float* __restrict__ par,
                              float* __restrict__ P)
{
    size_t i = (size_t)blockIdx.x * blockDim.x + threadIdx.x;
    const size_t SZ = (size_t)BQ * NM;
    if (i >= SZ) return;
    int b = (int)(i >> 13);   // / 8192
    float xv = X[i];
    const float* pr = par + b * 8;
    float p  = __expf(xv - pr[0]) / pr[1];
    float y2 = sigmoidf_(xv + pr[2]);
    float y3 = sigmoidf_(xv + pr[3]);
    float y4 = sigmoidf_(xv + pr[4]);
    float y5 = sigmoidf_(xv + pr[5]);
    P[i]          = p;
    P[SZ + i]     = y2 - p;
    P[2 * SZ + i] = y3 - y2;
    P[3 * SZ + i] = y4 - y3;
    P[4 * SZ + i] = y5 - y4;
}

// ---------------- in-place row softmax over N columns ----------------
__global__ void __launch_bounds__(256)
softmax_rows(float* __restrict__ L, int N)
{
    int b = blockIdx.x;
    float* r = L + (size_t)b * N;
    const int tid = threadIdx.x;
    const int lane = tid & 31;
    const int w = tid >> 5;
    __shared__ float redm[8], reds[8];
    __shared__ float s_m, s_sum;

    float m = -3.402823466e38f;
    for (int i = tid; i < N; i += 256) m = fmaxf(m, r[i]);
#pragma unroll
    for (int o = 16; o; o >>= 1) m = fmaxf(m, __shfl_xor_sync(0xffffffffu, m, o));
    if (lane == 0) redm[w] = m;
    __syncthreads();
    if (tid == 0) {
        float t = redm[0];
        for (int i = 1; i < 8; i++) t = fmaxf(t, redm[i]);
        s_m = t;
    }
    __syncthreads();
    m = s_m;

    float s = 0.f;
    for (int i = tid; i < N; i += 256) s += __expf(r[i] - m);
#pragma unroll
    for (int o = 16; o; o >>= 1) s += __shfl_xor_sync(0xffffffffu, s, o);
    if (lane == 0) reds[w] = s;
    __syncthreads();
    if (tid == 0) {
        float t = 0.f;
        for (int i = 0; i < 8; i++) t += reds[i];
        s_sum = t;
    }
    __syncthreads();
    float sum = s_sum;
    for (int i = tid; i < N; i += 256) r[i] = __expf(r[i] - m) / sum;
}

// ---------------- interleave planes -> output [B, D, 5] ----------------
__global__ void interleave_kernel(const float* __restrict__ Z, float* __restrict__ out, int BD)
{
    int i = blockIdx.x * blockDim.x + threadIdx.x;
    if (i >= BD * NCOL) return;
    int j = i % NCOL;
    int bd = i / NCOL;
    out[i] = Z[(size_t)j * BD + bd];
}

// ---------------- host launcher ----------------
extern "C" void kernel_launch(void* const* d_in, const int* in_sizes, int n_in,
                              void* d_out, int out_size)
{
    const float* x  = (const float*)d_in[0];   // [2048, 512]
    const float* Xi = (const float*)d_in[1];   // [8192, 512]
    float* out = (float*)d_out;                // [2048, 512, 5]

    const int B = BQ, N = NM, D = DD;

    float *pX, *pP, *pL, *pZ, *pm2, *px2, *pzn2, *ppar;
    cudaGetSymbolAddress((void**)&pX,  g_X);
    cudaGetSymbolAddress((void**)&pP,  g_P);
    cudaGetSymbolAddress((void**)&pL,  g_L);
    cudaGetSymbolAddress((void**)&pZ,  g_Z);
    cudaGetSymbolAddress((void**)&pm2, g_m2);
    cudaGetSymbolAddress((void**)&px2, g_x2);
    cudaGetSymbolAddress((void**)&pzn2,g_zn2);
    cudaGetSymbolAddress((void**)&ppar,g_par);

    // row norms
    rownorm2_kernel<<<N, 128>>>(Xi, pm2, D);
    rownorm2_kernel<<<B, 128>>>(x,  px2, D);

    // logits X = -max(dist^2, 0)   (fp32 GEMM, reference-order epilogue)
    dim3 gnt(N / 128, B / 128);
    sgemm_nt_ep<<<gnt, 256>>>(x, Xi, px2, pm2, pX, B, N, D);

    // per-row softmax stats + LML nus
    stats_kernel<<<B, 256>>>(pX, ppar);

    // ksm coefficient planes
    {
        size_t tot = (size_t)B * N;
        int blocks = (int)((tot + 255) / 256);
        planes_kernel<<<blocks, 256>>>(pX, ppar, pP);
    }

    // initial result planes: Z_j = P_j @ Xi
    dim3 gnn(D / 64, B / 64);
    for (int j = 0; j < NCOL; j++)
        sgemm_nn<<<gnn, 128>>>(pP + (size_t)j * B * N, Xi, pZ + (size_t)j * B * D, B, D, N);

    // hopfield steps
    for (int s = 0; s < 2; s++) {
        for (int j = 0; j < NCOL; j++) {
            float* Zj = pZ + (size_t)j * B * D;
            rownorm2_kernel<<<B, 128>>>(Zj, pzn2, D);
            sgemm_nt_ep<<<gnt, 256>>>(Zj, Xi, pzn2, pm2, pL, B, N, D);
            softmax_rows<<<B, 256>>>(pL, N);
            sgemm_nn<<<gnn, 128>>>(pL, Xi, Zj, B, D, N);
        }
    }

    // interleave to [B, D, 5]
    {
        int tot = B * D * NCOL;
        interleave_kernel<<<(tot + 255) / 256, 256>>>(pZ, out, B * D);
    }
}

// round 5
// speedup vs baseline: 1.0039x; 1.0039x over previous
#include <cuda_runtime.h>
#include <math.h>
#include <stdint.h>

// Problem constants (fixed by setup_inputs: x[2048,512], memories[8192,512], k=5, beta=1, steps=2)
#define BQ 2048
#define NM 8192
#define DD 512
#define NCOL 5
#define BISECT_ITERS 100
#define CAND_CAP 2040

// ---------------- scratch (device globals; no runtime allocation) ----------------
__device__ float g_X[(size_t)BQ * NM];                 // logits -dists  (67 MB)
__device__ float g_P[(size_t)NCOL * BQ * NM];          // ksm coefficient planes (335 MB)
__device__ float g_L[(size_t)BQ * NM];                 // hopfield logits/weights (67 MB)
__device__ float g_Z[(size_t)NCOL * BQ * DD];          // result planes (21 MB)
__device__ float g_m2[NM];
__device__ float g_x2[BQ];
__device__ float g_zn2[BQ];
__device__ float g_par[BQ * 8];                        // per row: max, sumexp, nu2..nu5

// ---------------- small helpers ----------------
__device__ __forceinline__ float sigmoidf_(float t) {
    return 1.0f / (1.0f + __expf(-t));
}

// ---------------- row squared-norms (fp32; order irrelevant: shift-invariant downstream) ----------------
__global__ void rownorm2_kernel(const float* __restrict__ A, float* __restrict__ out, int cols)
{
    int r = blockIdx.x;
    const float* a = A + (size_t)r * cols;
    float s = 0.f;
    for (int c = threadIdx.x; c < cols; c += blockDim.x) { float v = a[c]; s = fmaf(v, v, s); }
#pragma unroll
    for (int o = 16; o; o >>= 1) s += __shfl_xor_sync(0xffffffffu, s, o);
    __shared__ float red[4];
    if ((threadIdx.x & 31) == 0) red[threadIdx.x >> 5] = s;
    __syncthreads();
    if (threadIdx.x == 0) out[r] = red[0] + red[1] + red[2] + red[3];
}

// ---------------- NT SGEMM (fp32) with fused distance epilogue ----------------
// Mirrors reference association exactly: d = (arow[i] + bcol[j]) - 2*t;  logit = -max(d, 0)
__global__ void __launch_bounds__(256, 2)
sgemm_nt_ep(const float* __restrict__ A, const float* __restrict__ Bm,
            const float* __restrict__ arow, const float* __restrict__ bcol,
            float* __restrict__ C, int M, int N, int K)
{
    __shared__ float As[16][128];
    __shared__ float Bs[16][128];
    const int bm = blockIdx.y * 128;
    const int bn = blockIdx.x * 128;
    const int tid = threadIdx.x;
    const int tx = tid & 15;
    const int ty = tid >> 4;
    const int lr = tid >> 2;
    const int lc = (tid & 3) << 2;

    float acc[8][8];
#pragma unroll
    for (int i = 0; i < 8; i++)
#pragma unroll
        for (int j = 0; j < 8; j++) acc[i][j] = 0.f;

    for (int k0 = 0; k0 < K; k0 += 16) {
#pragma unroll
        for (int h = 0; h < 2; h++) {
            int r = lr + h * 64;
            float4 va = *(const float4*)(A + (size_t)(bm + r) * K + k0 + lc);
            As[lc + 0][r] = va.x; As[lc + 1][r] = va.y; As[lc + 2][r] = va.z; As[lc + 3][r] = va.w;
            float4 vb = *(const float4*)(Bm + (size_t)(bn + r) * K + k0 + lc);
            Bs[lc + 0][r] = vb.x; Bs[lc + 1][r] = vb.y; Bs[lc + 2][r] = vb.z; Bs[lc + 3][r] = vb.w;
        }
        __syncthreads();
#pragma unroll
        for (int kk = 0; kk < 16; kk++) {
            float a[8], b[8];
            float4 a0 = *(const float4*)&As[kk][ty * 8];
            float4 a1 = *(const float4*)&As[kk][ty * 8 + 4];
            float4 b0 = *(const float4*)&Bs[kk][tx * 8];
            float4 b1 = *(const float4*)&Bs[kk][tx * 8 + 4];
            a[0]=a0.x; a[1]=a0.y; a[2]=a0.z; a[3]=a0.w; a[4]=a1.x; a[5]=a1.y; a[6]=a1.z; a[7]=a1.w;
            b[0]=b0.x; b[1]=b0.y; b[2]=b0.z; b[3]=b0.w; b[4]=b1.x; b[5]=b1.y; b[6]=b1.z; b[7]=b1.w;
#pragma unroll
            for (int i = 0; i < 8; i++)
#pragma unroll
                for (int j = 0; j < 8; j++) acc[i][j] = fmaf(a[i], b[j], acc[i][j]);
        }
        __syncthreads();
    }

#pragma unroll
    for (int i = 0; i < 8; i++) {
        int gr = bm + ty * 8 + i;
        float ar = arow[gr];
#pragma unroll
        for (int j = 0; j < 8; j += 4) {
            int gc = bn + tx * 8 + j;
            float4 o;
            // reference op order: d = (x2 + m2) - 2*dot; max(d,0); logit = -d
            o.x = -fmaxf((ar + bcol[gc + 0]) - 2.f * acc[i][j + 0], 0.f);
            o.y = -fmaxf((ar + bcol[gc + 1]) - 2.f * acc[i][j + 1], 0.f);
            o.z = -fmaxf((ar + bcol[gc + 2]) - 2.f * acc[i][j + 2], 0.f);
            o.w = -fmaxf((ar + bcol[gc + 3]) - 2.f * acc[i][j + 3], 0.f);
            *(float4*)(C + (size_t)gr * N + gc) = o;
        }
    }
}

// ---------------- NN SGEMM (fp32): C[M,N] = A[M,K] @ B[K,N] ----------------
__global__ void __launch_bounds__(128)
sgemm_nn(const float* __restrict__ A, const float* __restrict__ Bm,
         float* __restrict__ C, int M, int N, int K)
{
    __shared__ float As[16][64];
    __shared__ float Bs[16][64];
    const int bm = blockIdx.y * 64;
    const int bn = blockIdx.x * 64;
    const int tid = threadIdx.x;
    const int tx = tid & 15;      // col group *4
    const int ty = tid >> 4;      // row group *8
    const int ar_ = tid >> 2;     // 0..31
    const int ac = (tid & 3) << 2;
    const int bkr = tid >> 4;     // 0..7
    const int bc = (tid & 15) << 2;

    float acc[8][4];
#pragma unroll
    for (int i = 0; i < 8; i++)
#pragma unroll
        for (int j = 0; j < 4; j++) acc[i][j] = 0.f;

    for (int k0 = 0; k0 < K; k0 += 16) {
#pragma unroll
        for (int h = 0; h < 2; h++) {
            int r = ar_ + h * 32;
            float4 va = *(const float4*)(A + (size_t)(bm + r) * K + k0 + ac);
            As[ac + 0][r] = va.x; As[ac + 1][r] = va.y; As[ac + 2][r] = va.z; As[ac + 3][r] = va.w;
            int kr = bkr + h * 8;
            float4 vb = *(const float4*)(Bm + (size_t)(k0 + kr) * N + bn + bc);
            *(float4*)&Bs[kr][bc] = vb;
        }
        __syncthreads();
#pragma unroll
        for (int kk = 0; kk < 16; kk++) {
            float4 a0 = *(const float4*)&As[kk][ty * 8];
            float4 a1 = *(const float4*)&As[kk][ty * 8 + 4];
            float4 b0 = *(const float4*)&Bs[kk][tx * 4];
            float a[8] = {a0.x, a0.y, a0.z, a0.w, a1.x, a1.y, a1.z, a1.w};
            float b[4] = {b0.x, b0.y, b0.z, b0.w};
#pragma unroll
            for (int i = 0; i < 8; i++)
#pragma unroll
                for (int j = 0; j < 4; j++) acc[i][j] = fmaf(a[i], b[j], acc[i][j]);
        }
        __syncthreads();
    }

#pragma unroll
    for (int i = 0; i < 8; i++) {
        int gr = bm + ty * 8 + i;
        float4 o = make_float4(acc[i][0], acc[i][1], acc[i][2], acc[i][3]);
        *(float4*)(C + (size_t)gr * N + bn + tx * 4) = o;
    }
}

// ---------------- per-row stats: max, sumexp, top-6, LML bisection ----------------
__global__ void __launch_bounds__(256)
stats_kernel(const float* __restrict__ X, float* __restrict__ par)
{
    __shared__ float s_row[NM];
    __shared__ float s_cand[CAND_CAP + 8];
    __shared__ float s_redf[8];
    __shared__ int   s_redi[8];
    __shared__ float s_topv[8];
    __shared__ int   s_cnt;
    __shared__ float s_max, s_sum;
    __shared__ int   s_total;

    const int b = blockIdx.x;
    const int tid = threadIdx.x;
    const int lane = tid & 31;
    const int w = tid >> 5;
    const float* x = X + (size_t)b * NM;

    // load row + local max
    float lmax = -3.402823466e38f;
    for (int i = tid; i < NM; i += 256) { float v = x[i]; s_row[i] = v; lmax = fmaxf(lmax, v); }
#pragma unroll
    for (int o = 16; o; o >>= 1) lmax = fmaxf(lmax, __shfl_xor_sync(0xffffffffu, lmax, o));
    if (lane == 0) s_redf[w] = lmax;
    __syncthreads();
    if (tid == 0) {
        float m = s_redf[0];
        for (int i = 1; i < 8; i++) m = fmaxf(m, s_redf[i]);
        s_max = m;
    }
    __syncthreads();
    const float rmax = s_max;

    // sum exp(x - max)
    float ls = 0.f;
    for (int i = tid; i < NM; i += 256) ls += __expf(s_row[i] - rmax);
#pragma unroll
    for (int o = 16; o; o >>= 1) ls += __shfl_xor_sync(0xffffffffu, ls, o);
    __syncthreads();
    if (lane == 0) s_redf[w] = ls;
    __syncthreads();
    if (tid == 0) {
        float t = 0.f;
        for (int i = 0; i < 8; i++) t += s_redf[i];
        s_sum = t;
    }

    // top-6 extraction (argmax passes; extracted entries replaced with -inf)
    for (int t6 = 0; t6 < 6; t6++) {
        __syncthreads();
        float lv = -3.402823466e38f; int li = 0;
        for (int i = tid; i < NM; i += 256) { float v = s_row[i]; if (v > lv) { lv = v; li = i; } }
#pragma unroll
        for (int o = 16; o; o >>= 1) {
            float ov = __shfl_xor_sync(0xffffffffu, lv, o);
            int   oi = __shfl_xor_sync(0xffffffffu, li, o);
            if (ov > lv || (ov == lv && oi < li)) { lv = ov; li = oi; }
        }
        if (lane == 0) { s_redf[w] = lv; s_redi[w] = li; }
        __syncthreads();
        if (tid == 0) {
            float bv = s_redf[0]; int bi = s_redi[0];
            for (int i = 1; i < 8; i++)
                if (s_redf[i] > bv || (s_redf[i] == bv && s_redi[i] < bi)) { bv = s_redf[i]; bi = s_redi[i]; }
            s_topv[t6] = bv;
            s_row[bi] = -3.402823466e38f;
        }
    }
    __syncthreads();

    // candidate compaction: values > top6 - 34  (dropped-sigmoid mass <= 8192*e^-27 ~ 1.5e-8)
    const float thr = s_topv[5] - 34.0f;
    if (tid == 0) s_cnt = 0;
    __syncthreads();
    for (int i = tid; i < NM; i += 256) {
        float v = s_row[i];
        if (v > thr) {
            int p = atomicAdd(&s_cnt, 1);
            if (p < CAND_CAP) s_cand[p] = v;
        }
    }
    __syncthreads();
    if (tid == 0) {
        int base = min(s_cnt, CAND_CAP);
        for (int i = 0; i < 6; i++) s_cand[base + i] = s_topv[i];
        s_total = base + 6;
    }
    __syncthreads();
    const int total = s_total;

    // bisection for nu_k, k = 2..5 (one warp each). Mirrors reference decisions.
    if (w < 4) {
        const int kk = w + 2;
        float lo = -s_topv[kk - 1] - 7.0f;
        float hi = -s_topv[kk] + 7.0f;
        for (int it = 0; it < BISECT_ITERS; it++) {
            float mid = 0.5f * (lo + hi);
            float s = 0.f;
            for (int c = lane; c < total; c += 32) s += sigmoidf_(s_cand[c] + mid);
#pragma unroll
            for (int o = 16; o; o >>= 1) s += __shfl_xor_sync(0xffffffffu, s, o);
            float f = s - (float)kk;
            if (f < 0.f) lo = mid; else hi = mid;
        }
        if (lane == 0) par[b * 8 + 2 + (kk - 2)] = 0.5f * (lo + hi);
    }
    if (tid == 0) {
        par[b * 8 + 0] = rmax;
        par[b * 8 + 1] = s_sum;
    }
}

// ---------------- coefficient planes: p, y2-p, y3-y2, y4-y3, y5-y4 ----------------
__global__ void planes_kernel(const float* __restrict__ X, const float* __restrict__ par,
                              float* __restrict__ P)
{
    size_t i = (size_t)blockIdx.x * blockDim.x + threadIdx.x;
    const size_t SZ = (size_t)BQ * NM;
    if (i >= SZ) return;
    int b = (int)(i >> 13);   // / 8192
    float xv = X[i];
    const float* pr = par + b * 8;
    float p  = __expf(xv - pr[0]) / pr[1];
    float y2 = sigmoidf_(xv + pr[2]);
    float y3 = sigmoidf_(xv + pr[3]);
    float y4 = sigmoidf_(xv + pr[4]);
    float y5 = sigmoidf_(xv + pr[5]);
    P[i]          = p;
    P[SZ + i]     = y2 - p;
    P[2 * SZ + i] = y3 - y2;
    P[3 * SZ + i] = y4 - y3;
    P[4 * SZ + i] = y5 - y4;
}

// ---------------- in-place row softmax over N columns ----------------
__global__ void __launch_bounds__(256)
softmax_rows(float* __restrict__ L, int N)
{
    int b = blockIdx.x;
    float* r = L + (size_t)b * N;
    const int tid = threadIdx.x;
    const int lane = tid & 31;
    const int w = tid >> 5;
    __shared__ float redm[8], reds[8];
    __shared__ float s_m, s_sum;

    float m = -3.402823466e38f;
    for (int i = tid; i < N; i += 256) m = fmaxf(m, r[i]);
#pragma unroll
    for (int o = 16; o; o >>= 1) m = fmaxf(m, __shfl_xor_sync(0xffffffffu, m, o));
    if (lane == 0) redm[w] = m;
    __syncthreads();
    if (tid == 0) {
        float t = redm[0];
        for (int i = 1; i < 8; i++) t = fmaxf(t, redm[i]);
        s_m = t;
    }
    __syncthreads();
    m = s_m;

    float s = 0.f;
    for (int i = tid; i < N; i += 256) s += __expf(r[i] - m);
#pragma unroll
    for (int o = 16; o; o >>= 1) s += __shfl_xor_sync(0xffffffffu, s, o);
    if (lane == 0) reds[w] = s;
    __syncthreads();
    if (tid == 0) {
        float t = 0.f;
        for (int i = 0; i < 8; i++) t += reds[i];
        s_sum = t;
    }
    __syncthreads();
    float sum = s_sum;
    for (int i = tid; i < N; i += 256) r[i] = __expf(r[i] - m) / sum;
}

// ---------------- interleave planes -> output [B, D, 5] ----------------
__global__ void interleave_kernel(const float* __restrict__ Z, float* __restrict__ out, int BD)
{
    int i = blockIdx.x * blockDim.x + threadIdx.x;
    if (i >= BD * NCOL) return;
    int j = i % NCOL;
    int bd = i / NCOL;
    out[i] = Z[(size_t)j * BD + bd];
}

// ---------------- host launcher ----------------
extern "C" void kernel_launch(void* const* d_in, const int* in_sizes, int n_in,
                              void* d_out, int out_size)
{
    const float* x  = (const float*)d_in[0];   // [2048, 512]
    const float* Xi = (const float*)d_in[1];   // [8192, 512]
    float* out = (float*)d_out;                // [2048, 512, 5]

    const int B = BQ, N = NM, D = DD;

    float *pX, *pP, *pL, *pZ, *pm2, *px2, *pzn2, *ppar;
    cudaGetSymbolAddress((void**)&pX,  g_X);
    cudaGetSymbolAddress((void**)&pP,  g_P);
    cudaGetSymbolAddress((void**)&pL,  g_L);
    cudaGetSymbolAddress((void**)&pZ,  g_Z);
    cudaGetSymbolAddress((void**)&pm2, g_m2);
    cudaGetSymbolAddress((void**)&px2, g_x2);
    cudaGetSymbolAddress((void**)&pzn2,g_zn2);
    cudaGetSymbolAddress((void**)&ppar,g_par);

    // row norms
    rownorm2_kernel<<<N, 128>>>(Xi, pm2, D);
    rownorm2_kernel<<<B, 128>>>(x,  px2, D);

    // logits X = -max(dist^2, 0)   (fp32 GEMM, reference-order epilogue)
    dim3 gnt(N / 128, B / 128);
    sgemm_nt_ep<<<gnt, 256>>>(x, Xi, px2, pm2, pX, B, N, D);

    // per-row softmax stats + LML nus
    stats_kernel<<<B, 256>>>(pX, ppar);

    // ksm coefficient planes
    {
        size_t tot = (size_t)B * N;
        int blocks = (int)((tot + 255) / 256);
        planes_kernel<<<blocks, 256>>>(pX, ppar, pP);
    }

    // initial result planes: Z_j = P_j @ Xi
    dim3 gnn(D / 64, B / 64);
    for (int j = 0; j < NCOL; j++)
        sgemm_nn<<<gnn, 128>>>(pP + (size_t)j * B * N, Xi, pZ + (size_t)j * B * D, B, D, N);

    // hopfield steps
    for (int s = 0; s < 2; s++) {
        for (int j = 0; j < NCOL; j++) {
            float* Zj = pZ + (size_t)j * B * D;
            rownorm2_kernel<<<B, 128>>>(Zj, pzn2, D);
            sgemm_nt_ep<<<gnt, 256>>>(Zj, Xi, pzn2, pm2, pL, B, N, D);
            softmax_rows<<<B, 256>>>(pL, N);
            sgemm_nn<<<gnn, 128>>>(pL, Xi, Zj, B, D, N);
        }
    }

    // interleave to [B, D, 5]
    {
        int tot = B * D * NCOL;
        interleave_kernel<<<(tot + 255) / 256, 256>>>(pZ, out, B * D);
    }
}